// round 15
// baseline (speedup 1.0000x reference)
#include <cuda_runtime.h>
#include <cuda_bf16.h>
#include <math.h>

// Problem constants
#define NSITES 1024
#define NC7 128              // 7-site codes (intermediate, for 14-composition)
#define NC5 32               // 5-site codes (smem table in mps)
#define N14 16384            // 14-site codes (L2 table)
#define N14STEPS 56
#define N5STEPS 48           // 56*14 + 48*5 = 1024 exactly
// B-fragment layout per entry: 512 u32 (128 uint4), idx = q*128 + lane*4 + j
__device__ unsigned g7_table[NC7 * 512];     // 7-site, B-layout
__device__ unsigned g7A_table[NC7 * 512];    // 7-site, A-layout (for build14)
__device__ unsigned g5_table[NC5 * 512];     // 5-site, B-layout
__device__ unsigned g14_table[N14 * 512];    // 14-site, 33.6 MB (L2-resident)

// ---------------------------------------------------------------------------
// build1: blocks 0..127 -> 7-site products (B-layout + A-layout copies);
//         blocks 128..159 -> 5-site products (g5_table).  Y = P - I, bf16.
// ---------------------------------------------------------------------------
__global__ void build_table_kernel(const float* __restrict__ A) {
    __shared__ float M[2][32][32];
    __shared__ float P[2][32][32];
    const int tid = threadIdx.x;          // 1024 threads
    const int r = tid >> 5, c = tid & 31;

    M[0][r][c] = A[r * 32 + c];
    M[1][r][c] = A[1024 + r * 32 + c];
    __syncthreads();

    const bool is7 = blockIdx.x < NC7;
    const int code = is7 ? blockIdx.x : (blockIdx.x - NC7);
    const int nsit = is7 ? 7 : 5;

    P[0][r][c] = M[code & 1][r][c];
    __syncthreads();

    int cur = 0;
    for (int t = 1; t < nsit; t++) {
        const int bsel = (code >> t) & 1;
        float acc = 0.f;
        #pragma unroll
        for (int k = 0; k < 32; k++) acc += P[cur][r][k] * M[bsel][k][c];
        P[1 - cur][r][c] = acc;
        cur ^= 1;
        __syncthreads();
    }
    if (tid < 512) {
        const int l = tid >> 4;           // lane
        const int ridx = tid & 15;        // reg 0..15
        const int tig = l & 3, g = l >> 2;
        const int q = ridx >> 2, j = ridx & 3;
        const int idx = q * 128 + l * 4 + j;
        {   // B-layout entry: vertical pair at (16kc+2tig+8h, 8nt+g)
            const int kc = ridx >> 3, nt = (ridx >> 1) & 3, h = ridx & 1;
            const int row = 16 * kc + 2 * tig + 8 * h;
            const int col = 8 * nt + g;
            const float lo = P[cur][row][col]     - (row     == col ? 1.f : 0.f);
            const float hi = P[cur][row + 1][col] - (row + 1 == col ? 1.f : 0.f);
            unsigned v;
            asm("cvt.rn.bf16x2.f32 %0, %1, %2;" : "=r"(v) : "f"(hi), "f"(lo));
            if (is7) g7_table[code * 512 + idx] = v;
            else     g5_table[code * 512 + idx] = v;
        }
        if (is7) {  // A-layout entry: horizontal pair, reg r = mt*8+kc*4+j'
            const int mt = ridx >> 3, kc = (ridx >> 2) & 1, jj = ridx & 3;
            const int o = jj >> 1, ih = jj & 1;
            const int row = g + 8 * ih + 16 * mt;
            const int col = 8 * (2 * kc + o) + 2 * tig;
            const float lo = P[cur][row][col]     - (row == col     ? 1.f : 0.f);
            const float hi = P[cur][row][col + 1] - (row == col + 1 ? 1.f : 0.f);
            unsigned v;
            asm("cvt.rn.bf16x2.f32 %0, %1, %2;" : "=r"(v) : "f"(hi), "f"(lo));
            g7A_table[code * 512 + idx] = v;
        }
    }
}

// ---------------------------------------------------------------------------
// Shared MMA helpers
// ---------------------------------------------------------------------------
__device__ __forceinline__ void mma_bf16(float* d, const unsigned* a,
                                         unsigned b0, unsigned b1) {
    asm("mma.sync.aligned.m16n8k16.row.col.f32.bf16.bf16.f32 "
        "{%0,%1,%2,%3}, {%4,%5,%6,%7}, {%8,%9}, {%0,%1,%2,%3};"
        : "+f"(d[0]), "+f"(d[1]), "+f"(d[2]), "+f"(d[3])
        : "r"(a[0]), "r"(a[1]), "r"(a[2]), "r"(a[3]), "r"(b0), "r"(b1));
}

__device__ __forceinline__ void mma_half(float x[32], const unsigned a[16],
                                         int abase, uint4 ta, uint4 tb) {
    #pragma unroll
    for (int mt = 0; mt < 2; mt++) {
        const unsigned* av = a + mt * 8 + abase;
        mma_bf16(x + mt*16 + 0,  av, ta.x, ta.y);
        mma_bf16(x + mt*16 + 4,  av, ta.z, ta.w);
        mma_bf16(x + mt*16 + 8,  av, tb.x, tb.y);
        mma_bf16(x + mt*16 + 12, av, tb.z, tb.w);
    }
}

__device__ __forceinline__ void cvt_a(unsigned a[16], const float x[32]) {
    #pragma unroll
    for (int mt = 0; mt < 2; mt++)
        #pragma unroll
        for (int kc = 0; kc < 2; kc++)
            #pragma unroll
            for (int j = 0; j < 4; j++) {
                const int o = j >> 1, ih = j & 1;
                const int xi = mt * 16 + (2 * kc + o) * 4 + 2 * ih;
                asm("cvt.rn.bf16x2.f32 %0, %1, %2;"
                    : "=r"(a[mt * 8 + kc * 4 + j])
                    : "f"(x[xi + 1]), "f"(x[xi]));
            }
}

// ---------------------------------------------------------------------------
// build14 (MMA): one 14-site entry per WARP.  Z = Ya@Yb + Ya + Yb  (7+7).
// ---------------------------------------------------------------------------
#define B14_WARPS 8
__global__ void __launch_bounds__(B14_WARPS * 32) build14_kernel() {
    __shared__ float Zs[B14_WARPS][32 * 34];   // row-major, stride 34
    const int lane = threadIdx.x & 31;
    const int warp = threadIdx.x >> 5;
    const int code = blockIdx.x * B14_WARPS + warp;
    const int ca = code & 127;            // first 7 sites
    const int cb = code >> 7;             // next 7 sites
    const int tig = lane & 3, g = lane >> 2;
    float* zs = Zs[warp];

    unsigned a[16], ybA[16];
    {
        const uint4* pa = reinterpret_cast<const uint4*>(g7A_table + ca * 512);
        const uint4* pb = reinterpret_cast<const uint4*>(g7A_table + cb * 512);
        #pragma unroll
        for (int q = 0; q < 4; q++) {
            const uint4 va = pa[q * 32 + lane];
            a[4*q+0] = va.x; a[4*q+1] = va.y; a[4*q+2] = va.z; a[4*q+3] = va.w;
            const uint4 vb = pb[q * 32 + lane];
            ybA[4*q+0] = vb.x; ybA[4*q+1] = vb.y; ybA[4*q+2] = vb.z; ybA[4*q+3] = vb.w;
        }
    }
    const uint4* pbB = reinterpret_cast<const uint4*>(g7_table + cb * 512);
    const uint4 b0 = pbB[lane],      b1 = pbB[32 + lane];
    const uint4 b2 = pbB[64 + lane], b3 = pbB[96 + lane];

    float x[32];
    #pragma unroll
    for (int i = 0; i < 32; i++) x[i] = 0.f;
    mma_half(x, a, 0, b0, b1);
    mma_half(x, a, 4, b2, b3);

    #pragma unroll
    for (int ridx = 0; ridx < 16; ridx++) {
        const int mt = ridx >> 3, kc = (ridx >> 2) & 1, jj = ridx & 3;
        const int o = jj >> 1, ih = jj & 1;
        const int xi = mt * 16 + (2 * kc + o) * 4 + 2 * ih;
        const unsigned ua = a[ridx], ub = ybA[ridx];
        x[xi]     += __uint_as_float(ua << 16) + __uint_as_float(ub << 16);
        x[xi + 1] += __uint_as_float(ua & 0xFFFF0000u)
                   + __uint_as_float(ub & 0xFFFF0000u);
    }

    #pragma unroll
    for (int mt = 0; mt < 2; mt++)
        #pragma unroll
        for (int nt = 0; nt < 4; nt++)
            #pragma unroll
            for (int ih = 0; ih < 2; ih++) {
                const int row = g + 8 * ih + 16 * mt;
                const int col = 8 * nt + 2 * tig;
                *reinterpret_cast<float2*>(zs + row * 34 + col) =
                    make_float2(x[mt*16 + nt*4 + 2*ih], x[mt*16 + nt*4 + 2*ih + 1]);
            }
    __syncwarp();

    #pragma unroll
    for (int q = 0; q < 4; q++) {
        unsigned v[4];
        #pragma unroll
        for (int j = 0; j < 4; j++) {
            const int ridx = 4 * q + j;
            const int kc = ridx >> 3, nt = (ridx >> 1) & 3, h = ridx & 1;
            const int row = 16 * kc + 2 * tig + 8 * h;
            const int col = 8 * nt + g;
            asm("cvt.rn.bf16x2.f32 %0, %1, %2;"
                : "=r"(v[j]) : "f"(zs[(row + 1) * 34 + col]), "f"(zs[row * 34 + col]));
        }
        *reinterpret_cast<uint4*>(g14_table + code * 512 + q * 128 + lane * 4) =
            make_uint4(v[0], v[1], v[2], v[3]);
    }
}

// ---------------------------------------------------------------------------
// Main kernel: ONE sample per warp, 28 warps/CTA.
// Hybrid: 56 x 14-site (L2 stream, 2-stage cp.async ring); first 48 pairs
// also do a 5-site step from the 64KB smem table. 56*14 + 48*5 = 1024.
// ---------------------------------------------------------------------------
__device__ __forceinline__ void step_from(const uint4* p, float x[32],
                                          unsigned a[16], int lane) {
    const uint4 t0 = p[lane],      t1 = p[32 + lane];
    const uint4 t2 = p[64 + lane], t3 = p[96 + lane];
    mma_half(x, a, 0, t0, t1);
    mma_half(x, a, 4, t2, t3);
    cvt_a(a, x);
}

__device__ __forceinline__ void prefetch_entry(unsigned dst,
                                               const unsigned* entry, int lane) {
    const unsigned* sp = entry + lane * 4;
    const unsigned dp = dst + lane * 16;
    asm volatile(
        "cp.async.cg.shared.global [%0], [%1], 16;\n\t"
        "cp.async.cg.shared.global [%2], [%3], 16;\n\t"
        "cp.async.cg.shared.global [%4], [%5], 16;\n\t"
        "cp.async.cg.shared.global [%6], [%7], 16;\n\t"
        :: "r"(dp),        "l"(sp),
           "r"(dp + 512),  "l"(sp + 128),
           "r"(dp + 1024), "l"(sp + 256),
           "r"(dp + 1536), "l"(sp + 384)
        : "memory");
}
#define CP_COMMIT()  asm volatile("cp.async.commit_group;" ::: "memory")
#define CP_WAIT1()   asm volatile("cp.async.wait_group 1;" ::: "memory")

#define NWARPS 28
#define G5_BYTES (NC5 * 512 * 4)              // 64 KB
#define RING_OFF G5_BYTES
#define RING_BYTES (NWARPS * 2 * 2048)        // 112 KB
#define MSK_OFF (RING_OFF + RING_BYTES)
#define MSK_BYTES (NWARPS * 32 * 4)           // 3.5 KB
#define CW14_OFF (MSK_OFF + MSK_BYTES)
#define CW14_BYTES (NWARPS * 64 * 2)          // 56 used, stride 64
#define CW5_OFF (CW14_OFF + CW14_BYTES)
#define CW5_BYTES (NWARPS * 64)               // 48 used, stride 64
#define SMEM_BYTES (CW5_OFF + CW5_BYTES)      // ~183 KB
#define GRID 148
#define NTHREADS (NWARPS * 32)                // 896

__global__ void __launch_bounds__(NTHREADS, 1)
mps_kernel(const float* __restrict__ s, float* __restrict__ out) {
    extern __shared__ unsigned char smem_raw[];
    uint4* g5tab = reinterpret_cast<uint4*>(smem_raw);
    const int lane = threadIdx.x & 31;
    const int warp = threadIdx.x >> 5;
    const int b = warp * GRID + blockIdx.x;   // one sample per warp
    const int g = lane >> 2, tig = lane & 3;

    {   // cooperative copy of the 5-site table
        const uint4* gt = reinterpret_cast<const uint4*>(g5_table);
        for (int i = threadIdx.x; i < NC5 * 128; i += NTHREADS)
            g5tab[i] = gt[i];
    }

    unsigned* mw = reinterpret_cast<unsigned*>(smem_raw + MSK_OFF) + warp * 32;
    unsigned short* cw14 =
        reinterpret_cast<unsigned short*>(smem_raw + CW14_OFF) + warp * 64;
    unsigned char* cw5 = smem_raw + CW5_OFF + warp * 64;

    // Prologue (warp-private): masks -> code sequences
    // pair i<48: 14-bit code @ bit 19i, 5-bit code @ 19i+14
    // pair i>=48: 14-bit code @ bit 912 + 14(i-48)
    if (b < 4096) {
        const float* srow = s + (size_t)b * NSITES;
        #pragma unroll 8
        for (int j = 0; j < 32; j++)
            mw[j] = __ballot_sync(0xffffffffu, srow[j * 32 + lane] > 0.f);
        __syncwarp();
        for (int t = lane; t < N14STEPS; t += 32) {
            int bit = (t < 48) ? 19 * t : 912 + 14 * (t - 48);
            int w = bit >> 5, sh = bit & 31;
            unsigned hi = (w < 31) ? mw[w + 1] : 0u;
            cw14[t] = (unsigned short)(__funnelshift_r(mw[w], hi, sh) & 0x3FFFu);
            if (t < 48) {
                bit += 14; w = bit >> 5; sh = bit & 31;
                hi = (w < 31) ? mw[w + 1] : 0u;
                cw5[t] = (unsigned char)(__funnelshift_r(mw[w], hi, sh) & 31u);
            }
        }
    }
    __syncthreads();            // g5 table ready
    if (b >= 4096) return;

    uint4* rp = reinterpret_cast<uint4*>(smem_raw + RING_OFF + warp * 4096);
    const unsigned ring_s = (unsigned)__cvta_generic_to_shared(rp);

    // Init M = I in C-fragment layout
    float x[32];
    #pragma unroll
    for (int mt = 0; mt < 2; mt++)
        #pragma unroll
        for (int nt = 0; nt < 4; nt++)
            #pragma unroll
            for (int i = 0; i < 4; i++) {
                const int row = g + 8 * (i >> 1) + 16 * mt;
                const int col = 8 * nt + 2 * tig + (i & 1);
                x[mt*16 + nt*4 + i] = (row == col) ? 1.f : 0.f;
            }

    // Ring prologue
    prefetch_entry(ring_s,        g14_table + (int)cw14[0] * 512, lane);
    CP_COMMIT();
    prefetch_entry(ring_s + 2048, g14_table + (int)cw14[1] * 512, lane);
    CP_COMMIT();
    unsigned a[16];
    cvt_a(a, x);

    for (int i = 0; i < N14STEPS; i++) {
        CP_WAIT1();                            // this 14-entry is resident
        const uint4* p = rp + (i & 1) * 128;
        const uint4 t0 = p[lane],      t1 = p[32 + lane];
        const uint4 t2 = p[64 + lane], t3 = p[96 + lane];
        if (i + 2 < N14STEPS)
            prefetch_entry(ring_s + (i & 1) * 2048,
                           g14_table + (int)cw14[i + 2] * 512, lane);
        CP_COMMIT();                           // uniform group accounting
        mma_half(x, a, 0, t0, t1);             // 14-site step
        mma_half(x, a, 4, t2, t3);
        cvt_a(a, x);
        if (i < N5STEPS)
            step_from(g5tab + (int)cw5[i] * 128, x, a, lane);   // 5-site step
    }

    // trace(M)
    float tr = 0.f;
    #pragma unroll
    for (int mt = 0; mt < 2; mt++)
        #pragma unroll
        for (int nt = 0; nt < 4; nt++)
            #pragma unroll
            for (int i = 0; i < 4; i++) {
                const int row = g + 8 * (i >> 1) + 16 * mt;
                const int col = 8 * nt + 2 * tig + (i & 1);
                if (row == col) tr += x[mt*16 + nt*4 + i];
            }
    #pragma unroll
    for (int off = 16; off; off >>= 1)
        tr += __shfl_xor_sync(0xffffffffu, tr, off);

    if (lane == 0) out[b] = logf(tr);
}

// ---------------------------------------------------------------------------
extern "C" void kernel_launch(void* const* d_in, const int* in_sizes, int n_in,
                              void* d_out, int out_size) {
    const float* s = (const float*)d_in[0];   // [4096, 1024] fp32
    const float* A = (const float*)d_in[1];   // [2, 32, 32] fp32
    float* out = (float*)d_out;               // [4096] fp32

    static bool attr_set = false;
    if (!attr_set) {
        cudaFuncSetAttribute(mps_kernel,
                             cudaFuncAttributeMaxDynamicSharedMemorySize,
                             SMEM_BYTES);
        attr_set = true;
    }

    build_table_kernel<<<NC7 + NC5, 1024>>>(A);
    build14_kernel<<<N14 / B14_WARPS, B14_WARPS * 32>>>();
    mps_kernel<<<GRID, NTHREADS, SMEM_BYTES>>>(s, out);
}

// round 16
// speedup vs baseline: 1.0216x; 1.0216x over previous
#include <cuda_runtime.h>
#include <cuda_bf16.h>
#include <math.h>

// Problem constants
#define NSITES 1024
#define NB3 8                // 3-site codes (base)
#define NB4 16               // 4-site codes (base)
#define NC5 32               // 5-site codes (smem table in mps)
#define NC7 128              // 7-site codes = 4(low) compose 3(high)
#define N14 16384            // 14-site codes (L2 table)
#define N14STEPS 56
#define N5STEPS 48           // 56*14 + 48*5 = 1024 exactly
// B-fragment layout per entry: 512 u32 (128 uint4), idx = q*128 + lane*4 + j
__device__ unsigned g3B[NB3 * 512],  g3A[NB3 * 512];
__device__ unsigned g4B[NB4 * 512],  g4A[NB4 * 512];
__device__ unsigned g5_table[NC5 * 512];
__device__ unsigned g7B[NC7 * 512],  g7A[NC7 * 512];
__device__ unsigned g14_table[N14 * 512];    // 33.6 MB (L2-resident)

// ---------------------------------------------------------------------------
// build_base (serial): blocks 0..7 -> 3-site (B+A); 8..23 -> 4-site (B+A);
// 24..55 -> 5-site (B only).  Y = P - I as bf16 fragments.
// ---------------------------------------------------------------------------
__global__ void build_base_kernel(const float* __restrict__ A) {
    __shared__ float M[2][32][32];
    __shared__ float P[2][32][32];
    const int tid = threadIdx.x;          // 1024 threads
    const int r = tid >> 5, c = tid & 31;

    M[0][r][c] = A[r * 32 + c];
    M[1][r][c] = A[1024 + r * 32 + c];
    __syncthreads();

    int code, nsit, kind;                 // kind: 0=3site,1=4site,2=5site
    if (blockIdx.x < NB3)            { code = blockIdx.x;       nsit = 3; kind = 0; }
    else if (blockIdx.x < NB3 + NB4) { code = blockIdx.x - NB3; nsit = 4; kind = 1; }
    else                             { code = blockIdx.x - NB3 - NB4; nsit = 5; kind = 2; }

    P[0][r][c] = M[code & 1][r][c];
    __syncthreads();

    int cur = 0;
    for (int t = 1; t < nsit; t++) {
        const int bsel = (code >> t) & 1;
        float acc = 0.f;
        #pragma unroll
        for (int k = 0; k < 32; k++) acc += P[cur][r][k] * M[bsel][k][c];
        P[1 - cur][r][c] = acc;
        cur ^= 1;
        __syncthreads();
    }
    if (tid < 512) {
        const int l = tid >> 4;           // lane
        const int ridx = tid & 15;        // reg 0..15
        const int tig = l & 3, g = l >> 2;
        const int q = ridx >> 2, j = ridx & 3;
        const int idx = q * 128 + l * 4 + j;
        {   // B-layout: vertical pair at (16kc+2tig+8h, 8nt+g)
            const int kc = ridx >> 3, nt = (ridx >> 1) & 3, h = ridx & 1;
            const int row = 16 * kc + 2 * tig + 8 * h;
            const int col = 8 * nt + g;
            const float lo = P[cur][row][col]     - (row     == col ? 1.f : 0.f);
            const float hi = P[cur][row + 1][col] - (row + 1 == col ? 1.f : 0.f);
            unsigned v;
            asm("cvt.rn.bf16x2.f32 %0, %1, %2;" : "=r"(v) : "f"(hi), "f"(lo));
            if (kind == 0)      g3B[code * 512 + idx] = v;
            else if (kind == 1) g4B[code * 512 + idx] = v;
            else                g5_table[code * 512 + idx] = v;
        }
        if (kind < 2) {  // A-layout: horizontal pair, reg r = mt*8+kc*4+j'
            const int mt = ridx >> 3, kc = (ridx >> 2) & 1, jj = ridx & 3;
            const int o = jj >> 1, ih = jj & 1;
            const int row = g + 8 * ih + 16 * mt;
            const int col = 8 * (2 * kc + o) + 2 * tig;
            const float lo = P[cur][row][col]     - (row == col     ? 1.f : 0.f);
            const float hi = P[cur][row][col + 1] - (row == col + 1 ? 1.f : 0.f);
            unsigned v;
            asm("cvt.rn.bf16x2.f32 %0, %1, %2;" : "=r"(v) : "f"(hi), "f"(lo));
            if (kind == 0) g3A[code * 512 + idx] = v;
            else           g4A[code * 512 + idx] = v;
        }
    }
}

// ---------------------------------------------------------------------------
// Shared MMA helpers
// ---------------------------------------------------------------------------
__device__ __forceinline__ void mma_bf16(float* d, const unsigned* a,
                                         unsigned b0, unsigned b1) {
    asm("mma.sync.aligned.m16n8k16.row.col.f32.bf16.bf16.f32 "
        "{%0,%1,%2,%3}, {%4,%5,%6,%7}, {%8,%9}, {%0,%1,%2,%3};"
        : "+f"(d[0]), "+f"(d[1]), "+f"(d[2]), "+f"(d[3])
        : "r"(a[0]), "r"(a[1]), "r"(a[2]), "r"(a[3]), "r"(b0), "r"(b1));
}

__device__ __forceinline__ void mma_half(float x[32], const unsigned a[16],
                                         int abase, uint4 ta, uint4 tb) {
    #pragma unroll
    for (int mt = 0; mt < 2; mt++) {
        const unsigned* av = a + mt * 8 + abase;
        mma_bf16(x + mt*16 + 0,  av, ta.x, ta.y);
        mma_bf16(x + mt*16 + 4,  av, ta.z, ta.w);
        mma_bf16(x + mt*16 + 8,  av, tb.x, tb.y);
        mma_bf16(x + mt*16 + 12, av, tb.z, tb.w);
    }
}

__device__ __forceinline__ void cvt_a(unsigned a[16], const float x[32]) {
    #pragma unroll
    for (int mt = 0; mt < 2; mt++)
        #pragma unroll
        for (int kc = 0; kc < 2; kc++)
            #pragma unroll
            for (int j = 0; j < 4; j++) {
                const int o = j >> 1, ih = j & 1;
                const int xi = mt * 16 + (2 * kc + o) * 4 + 2 * ih;
                asm("cvt.rn.bf16x2.f32 %0, %1, %2;"
                    : "=r"(a[mt * 8 + kc * 4 + j])
                    : "f"(x[xi + 1]), "f"(x[xi]));
            }
}

// ---------------------------------------------------------------------------
// Warp MMA composition: Z = Ya@Yb + Ya + Yb (deviations in, deviation out).
// Reads A-layout of Ya & Yb and B-layout of Yb; result in smem tile zs
// (row-major, stride 34), then emitted as B-layout (+ optionally A-layout).
// ---------------------------------------------------------------------------
__device__ __forceinline__ void compose_to_tile(
    const unsigned* tabAa, const unsigned* tabAb, const unsigned* tabBb,
    float* zs, int lane) {
    const int tig = lane & 3, g = lane >> 2;
    unsigned a[16], ybA[16];
    {
        const uint4* pa = reinterpret_cast<const uint4*>(tabAa);
        const uint4* pb = reinterpret_cast<const uint4*>(tabAb);
        #pragma unroll
        for (int q = 0; q < 4; q++) {
            const uint4 va = pa[q * 32 + lane];
            a[4*q+0] = va.x; a[4*q+1] = va.y; a[4*q+2] = va.z; a[4*q+3] = va.w;
            const uint4 vb = pb[q * 32 + lane];
            ybA[4*q+0] = vb.x; ybA[4*q+1] = vb.y; ybA[4*q+2] = vb.z; ybA[4*q+3] = vb.w;
        }
    }
    const uint4* pbB = reinterpret_cast<const uint4*>(tabBb);
    const uint4 b0 = pbB[lane],      b1 = pbB[32 + lane];
    const uint4 b2 = pbB[64 + lane], b3 = pbB[96 + lane];

    float x[32];
    #pragma unroll
    for (int i = 0; i < 32; i++) x[i] = 0.f;
    mma_half(x, a, 0, b0, b1);
    mma_half(x, a, 4, b2, b3);

    #pragma unroll
    for (int ridx = 0; ridx < 16; ridx++) {
        const int mt = ridx >> 3, kc = (ridx >> 2) & 1, jj = ridx & 3;
        const int o = jj >> 1, ih = jj & 1;
        const int xi = mt * 16 + (2 * kc + o) * 4 + 2 * ih;
        const unsigned ua = a[ridx], ub = ybA[ridx];
        x[xi]     += __uint_as_float(ua << 16) + __uint_as_float(ub << 16);
        x[xi + 1] += __uint_as_float(ua & 0xFFFF0000u)
                   + __uint_as_float(ub & 0xFFFF0000u);
    }

    #pragma unroll
    for (int mt = 0; mt < 2; mt++)
        #pragma unroll
        for (int nt = 0; nt < 4; nt++)
            #pragma unroll
            for (int ih = 0; ih < 2; ih++) {
                const int row = g + 8 * ih + 16 * mt;
                const int col = 8 * nt + 2 * tig;
                *reinterpret_cast<float2*>(zs + row * 34 + col) =
                    make_float2(x[mt*16 + nt*4 + 2*ih], x[mt*16 + nt*4 + 2*ih + 1]);
            }
    __syncwarp();
}

template <bool WITH_A>
__device__ __forceinline__ void emit_entry(const float* zs, unsigned* outB,
                                           unsigned* outA, int lane) {
    const int tig = lane & 3, g = lane >> 2;
    #pragma unroll
    for (int q = 0; q < 4; q++) {
        unsigned v[4];
        #pragma unroll
        for (int j = 0; j < 4; j++) {
            const int ridx = 4 * q + j;
            const int kc = ridx >> 3, nt = (ridx >> 1) & 3, h = ridx & 1;
            const int row = 16 * kc + 2 * tig + 8 * h;
            const int col = 8 * nt + g;
            asm("cvt.rn.bf16x2.f32 %0, %1, %2;"
                : "=r"(v[j]) : "f"(zs[(row + 1) * 34 + col]), "f"(zs[row * 34 + col]));
        }
        *reinterpret_cast<uint4*>(outB + q * 128 + lane * 4) =
            make_uint4(v[0], v[1], v[2], v[3]);
        if (WITH_A) {
            unsigned w[4];
            #pragma unroll
            for (int j = 0; j < 4; j++) {
                const int ridx = 4 * q + j;
                const int mt = ridx >> 3, kc = (ridx >> 2) & 1, jj = ridx & 3;
                const int o = jj >> 1, ih = jj & 1;
                const int row = g + 8 * ih + 16 * mt;
                const int col = 8 * (2 * kc + o) + 2 * tig;
                asm("cvt.rn.bf16x2.f32 %0, %1, %2;"
                    : "=r"(w[j]) : "f"(zs[row * 34 + col + 1]), "f"(zs[row * 34 + col]));
            }
            *reinterpret_cast<uint4*>(outA + q * 128 + lane * 4) =
                make_uint4(w[0], w[1], w[2], w[3]);
        }
    }
}

// compose7: 7 = 4(low bits) o 3(high bits); 128 warps, emits B + A layouts
#define C7_WARPS 8
__global__ void __launch_bounds__(C7_WARPS * 32) compose7_kernel() {
    __shared__ float Zs[C7_WARPS][32 * 34];
    const int lane = threadIdx.x & 31;
    const int warp = threadIdx.x >> 5;
    const int code = blockIdx.x * C7_WARPS + warp;
    const int ca = code & 15;             // first 4 sites
    const int cb = code >> 4;             // next 3 sites
    compose_to_tile(g4A + ca * 512, g3A + cb * 512, g3B + cb * 512,
                    Zs[warp], lane);
    emit_entry<true>(Zs[warp], g7B + code * 512, g7A + code * 512, lane);
}

// build14: 14 = 7(low) o 7(high); 16384 warps, emits B layout only
#define B14_WARPS 8
__global__ void __launch_bounds__(B14_WARPS * 32) build14_kernel() {
    __shared__ float Zs[B14_WARPS][32 * 34];
    const int lane = threadIdx.x & 31;
    const int warp = threadIdx.x >> 5;
    const int code = blockIdx.x * B14_WARPS + warp;
    const int ca = code & 127;            // first 7 sites
    const int cb = code >> 7;             // next 7 sites
    compose_to_tile(g7A + ca * 512, g7A + cb * 512, g7B + cb * 512,
                    Zs[warp], lane);
    emit_entry<false>(Zs[warp], g14_table + code * 512, nullptr, lane);
}

// ---------------------------------------------------------------------------
// Main kernel (UNCHANGED from R15): ONE sample per warp, 28 warps/CTA.
// Hybrid: 56 x 14-site (L2 stream, 2-stage cp.async ring); first 48 pairs
// also do a 5-site step from the 64KB smem table. 56*14 + 48*5 = 1024.
// ---------------------------------------------------------------------------
__device__ __forceinline__ void step_from(const uint4* p, float x[32],
                                          unsigned a[16], int lane) {
    const uint4 t0 = p[lane],      t1 = p[32 + lane];
    const uint4 t2 = p[64 + lane], t3 = p[96 + lane];
    mma_half(x, a, 0, t0, t1);
    mma_half(x, a, 4, t2, t3);
    cvt_a(a, x);
}

__device__ __forceinline__ void prefetch_entry(unsigned dst,
                                               const unsigned* entry, int lane) {
    const unsigned* sp = entry + lane * 4;
    const unsigned dp = dst + lane * 16;
    asm volatile(
        "cp.async.cg.shared.global [%0], [%1], 16;\n\t"
        "cp.async.cg.shared.global [%2], [%3], 16;\n\t"
        "cp.async.cg.shared.global [%4], [%5], 16;\n\t"
        "cp.async.cg.shared.global [%6], [%7], 16;\n\t"
        :: "r"(dp),        "l"(sp),
           "r"(dp + 512),  "l"(sp + 128),
           "r"(dp + 1024), "l"(sp + 256),
           "r"(dp + 1536), "l"(sp + 384)
        : "memory");
}
#define CP_COMMIT()  asm volatile("cp.async.commit_group;" ::: "memory")
#define CP_WAIT1()   asm volatile("cp.async.wait_group 1;" ::: "memory")

#define NWARPS 28
#define G5_BYTES (NC5 * 512 * 4)              // 64 KB
#define RING_OFF G5_BYTES
#define RING_BYTES (NWARPS * 2 * 2048)        // 112 KB
#define MSK_OFF (RING_OFF + RING_BYTES)
#define MSK_BYTES (NWARPS * 32 * 4)           // 3.5 KB
#define CW14_OFF (MSK_OFF + MSK_BYTES)
#define CW14_BYTES (NWARPS * 64 * 2)          // 56 used, stride 64
#define CW5_OFF (CW14_OFF + CW14_BYTES)
#define CW5_BYTES (NWARPS * 64)               // 48 used, stride 64
#define SMEM_BYTES (CW5_OFF + CW5_BYTES)      // ~183 KB
#define GRID 148
#define NTHREADS (NWARPS * 32)                // 896

__global__ void __launch_bounds__(NTHREADS, 1)
mps_kernel(const float* __restrict__ s, float* __restrict__ out) {
    extern __shared__ unsigned char smem_raw[];
    uint4* g5tab = reinterpret_cast<uint4*>(smem_raw);
    const int lane = threadIdx.x & 31;
    const int warp = threadIdx.x >> 5;
    const int b = warp * GRID + blockIdx.x;   // one sample per warp
    const int g = lane >> 2, tig = lane & 3;

    {   // cooperative copy of the 5-site table
        const uint4* gt = reinterpret_cast<const uint4*>(g5_table);
        for (int i = threadIdx.x; i < NC5 * 128; i += NTHREADS)
            g5tab[i] = gt[i];
    }

    unsigned* mw = reinterpret_cast<unsigned*>(smem_raw + MSK_OFF) + warp * 32;
    unsigned short* cw14 =
        reinterpret_cast<unsigned short*>(smem_raw + CW14_OFF) + warp * 64;
    unsigned char* cw5 = smem_raw + CW5_OFF + warp * 64;

    // Prologue (warp-private): masks -> code sequences
    // pair i<48: 14-bit code @ bit 19i, 5-bit code @ 19i+14
    // pair i>=48: 14-bit code @ bit 912 + 14(i-48)
    if (b < 4096) {
        const float* srow = s + (size_t)b * NSITES;
        #pragma unroll 8
        for (int j = 0; j < 32; j++)
            mw[j] = __ballot_sync(0xffffffffu, srow[j * 32 + lane] > 0.f);
        __syncwarp();
        for (int t = lane; t < N14STEPS; t += 32) {
            int bit = (t < 48) ? 19 * t : 912 + 14 * (t - 48);
            int w = bit >> 5, sh = bit & 31;
            unsigned hi = (w < 31) ? mw[w + 1] : 0u;
            cw14[t] = (unsigned short)(__funnelshift_r(mw[w], hi, sh) & 0x3FFFu);
            if (t < 48) {
                bit += 14; w = bit >> 5; sh = bit & 31;
                hi = (w < 31) ? mw[w + 1] : 0u;
                cw5[t] = (unsigned char)(__funnelshift_r(mw[w], hi, sh) & 31u);
            }
        }
    }
    __syncthreads();            // g5 table ready
    if (b >= 4096) return;

    uint4* rp = reinterpret_cast<uint4*>(smem_raw + RING_OFF + warp * 4096);
    const unsigned ring_s = (unsigned)__cvta_generic_to_shared(rp);

    // Init M = I in C-fragment layout
    float x[32];
    #pragma unroll
    for (int mt = 0; mt < 2; mt++)
        #pragma unroll
        for (int nt = 0; nt < 4; nt++)
            #pragma unroll
            for (int i = 0; i < 4; i++) {
                const int row = g + 8 * (i >> 1) + 16 * mt;
                const int col = 8 * nt + 2 * tig + (i & 1);
                x[mt*16 + nt*4 + i] = (row == col) ? 1.f : 0.f;
            }

    // Ring prologue
    prefetch_entry(ring_s,        g14_table + (int)cw14[0] * 512, lane);
    CP_COMMIT();
    prefetch_entry(ring_s + 2048, g14_table + (int)cw14[1] * 512, lane);
    CP_COMMIT();
    unsigned a[16];
    cvt_a(a, x);

    for (int i = 0; i < N14STEPS; i++) {
        CP_WAIT1();                            // this 14-entry is resident
        const uint4* p = rp + (i & 1) * 128;
        const uint4 t0 = p[lane],      t1 = p[32 + lane];
        const uint4 t2 = p[64 + lane], t3 = p[96 + lane];
        if (i + 2 < N14STEPS)
            prefetch_entry(ring_s + (i & 1) * 2048,
                           g14_table + (int)cw14[i + 2] * 512, lane);
        CP_COMMIT();                           // uniform group accounting
        mma_half(x, a, 0, t0, t1);             // 14-site step
        mma_half(x, a, 4, t2, t3);
        cvt_a(a, x);
        if (i < N5STEPS)
            step_from(g5tab + (int)cw5[i] * 128, x, a, lane);   // 5-site step
    }

    // trace(M)
    float tr = 0.f;
    #pragma unroll
    for (int mt = 0; mt < 2; mt++)
        #pragma unroll
        for (int nt = 0; nt < 4; nt++)
            #pragma unroll
            for (int i = 0; i < 4; i++) {
                const int row = g + 8 * (i >> 1) + 16 * mt;
                const int col = 8 * nt + 2 * tig + (i & 1);
                if (row == col) tr += x[mt*16 + nt*4 + i];
            }
    #pragma unroll
    for (int off = 16; off; off >>= 1)
        tr += __shfl_xor_sync(0xffffffffu, tr, off);

    if (lane == 0) out[b] = logf(tr);
}

// ---------------------------------------------------------------------------
extern "C" void kernel_launch(void* const* d_in, const int* in_sizes, int n_in,
                              void* d_out, int out_size) {
    const float* s = (const float*)d_in[0];   // [4096, 1024] fp32
    const float* A = (const float*)d_in[1];   // [2, 32, 32] fp32
    float* out = (float*)d_out;               // [4096] fp32

    static bool attr_set = false;
    if (!attr_set) {
        cudaFuncSetAttribute(mps_kernel,
                             cudaFuncAttributeMaxDynamicSharedMemorySize,
                             SMEM_BYTES);
        attr_set = true;
    }

    build_base_kernel<<<NB3 + NB4 + NC5, 1024>>>(A);
    compose7_kernel<<<NC7 / C7_WARPS, C7_WARPS * 32>>>();
    build14_kernel<<<N14 / B14_WARPS, B14_WARPS * 32>>>();
    mps_kernel<<<GRID, NTHREADS, SMEM_BYTES>>>(s, out);
}

// round 17
// speedup vs baseline: 1.0413x; 1.0193x over previous
#include <cuda_runtime.h>
#include <cuda_bf16.h>
#include <math.h>

// Problem constants
#define NSITES 1024
#define NB3 8                // 3-site codes (base)
#define NB4 16               // 4-site codes (base + mps smem table)
#define NC7 128              // 7-site codes = 4(low) compose 3(high)
#define N14 16384            // 14-site codes (L2 table)
#define N14STEPS 64
#define N4STEPS 32           // 64*14 + 32*4 = 1024 exactly
// B-fragment layout per entry: 512 u32 (128 uint4), idx = q*128 + lane*4 + j
__device__ unsigned g3B[NB3 * 512],  g3A[NB3 * 512];
__device__ unsigned g4B[NB4 * 512],  g4A[NB4 * 512];
__device__ unsigned g7B[NC7 * 512],  g7A[NC7 * 512];
__device__ unsigned g14_table[N14 * 512];    // 33.6 MB (L2-resident)

// ---------------------------------------------------------------------------
// build_base (serial): blocks 0..7 -> 3-site (B+A); 8..23 -> 4-site (B+A).
// Y = P - I as bf16 fragments.
// ---------------------------------------------------------------------------
__global__ void build_base_kernel(const float* __restrict__ A) {
    __shared__ float M[2][32][32];
    __shared__ float P[2][32][32];
    const int tid = threadIdx.x;          // 1024 threads
    const int r = tid >> 5, c = tid & 31;

    M[0][r][c] = A[r * 32 + c];
    M[1][r][c] = A[1024 + r * 32 + c];
    __syncthreads();

    const bool is3 = blockIdx.x < NB3;
    const int code = is3 ? blockIdx.x : (blockIdx.x - NB3);
    const int nsit = is3 ? 3 : 4;

    P[0][r][c] = M[code & 1][r][c];
    __syncthreads();

    int cur = 0;
    for (int t = 1; t < nsit; t++) {
        const int bsel = (code >> t) & 1;
        float acc = 0.f;
        #pragma unroll
        for (int k = 0; k < 32; k++) acc += P[cur][r][k] * M[bsel][k][c];
        P[1 - cur][r][c] = acc;
        cur ^= 1;
        __syncthreads();
    }
    if (tid < 512) {
        const int l = tid >> 4;           // lane
        const int ridx = tid & 15;        // reg 0..15
        const int tig = l & 3, g = l >> 2;
        const int q = ridx >> 2, j = ridx & 3;
        const int idx = q * 128 + l * 4 + j;
        {   // B-layout: vertical pair at (16kc+2tig+8h, 8nt+g)
            const int kc = ridx >> 3, nt = (ridx >> 1) & 3, h = ridx & 1;
            const int row = 16 * kc + 2 * tig + 8 * h;
            const int col = 8 * nt + g;
            const float lo = P[cur][row][col]     - (row     == col ? 1.f : 0.f);
            const float hi = P[cur][row + 1][col] - (row + 1 == col ? 1.f : 0.f);
            unsigned v;
            asm("cvt.rn.bf16x2.f32 %0, %1, %2;" : "=r"(v) : "f"(hi), "f"(lo));
            if (is3) g3B[code * 512 + idx] = v;
            else     g4B[code * 512 + idx] = v;
        }
        {   // A-layout: horizontal pair, reg r = mt*8+kc*4+j'
            const int mt = ridx >> 3, kc = (ridx >> 2) & 1, jj = ridx & 3;
            const int o = jj >> 1, ih = jj & 1;
            const int row = g + 8 * ih + 16 * mt;
            const int col = 8 * (2 * kc + o) + 2 * tig;
            const float lo = P[cur][row][col]     - (row == col     ? 1.f : 0.f);
            const float hi = P[cur][row][col + 1] - (row == col + 1 ? 1.f : 0.f);
            unsigned v;
            asm("cvt.rn.bf16x2.f32 %0, %1, %2;" : "=r"(v) : "f"(hi), "f"(lo));
            if (is3) g3A[code * 512 + idx] = v;
            else     g4A[code * 512 + idx] = v;
        }
    }
}

// ---------------------------------------------------------------------------
// Shared MMA helpers
// ---------------------------------------------------------------------------
__device__ __forceinline__ void mma_bf16(float* d, const unsigned* a,
                                         unsigned b0, unsigned b1) {
    asm("mma.sync.aligned.m16n8k16.row.col.f32.bf16.bf16.f32 "
        "{%0,%1,%2,%3}, {%4,%5,%6,%7}, {%8,%9}, {%0,%1,%2,%3};"
        : "+f"(d[0]), "+f"(d[1]), "+f"(d[2]), "+f"(d[3])
        : "r"(a[0]), "r"(a[1]), "r"(a[2]), "r"(a[3]), "r"(b0), "r"(b1));
}

__device__ __forceinline__ void mma_half(float x[32], const unsigned a[16],
                                         int abase, uint4 ta, uint4 tb) {
    #pragma unroll
    for (int mt = 0; mt < 2; mt++) {
        const unsigned* av = a + mt * 8 + abase;
        mma_bf16(x + mt*16 + 0,  av, ta.x, ta.y);
        mma_bf16(x + mt*16 + 4,  av, ta.z, ta.w);
        mma_bf16(x + mt*16 + 8,  av, tb.x, tb.y);
        mma_bf16(x + mt*16 + 12, av, tb.z, tb.w);
    }
}

__device__ __forceinline__ void cvt_a(unsigned a[16], const float x[32]) {
    #pragma unroll
    for (int mt = 0; mt < 2; mt++)
        #pragma unroll
        for (int kc = 0; kc < 2; kc++)
            #pragma unroll
            for (int j = 0; j < 4; j++) {
                const int o = j >> 1, ih = j & 1;
                const int xi = mt * 16 + (2 * kc + o) * 4 + 2 * ih;
                asm("cvt.rn.bf16x2.f32 %0, %1, %2;"
                    : "=r"(a[mt * 8 + kc * 4 + j])
                    : "f"(x[xi + 1]), "f"(x[xi]));
            }
}

// ---------------------------------------------------------------------------
// Warp MMA composition: Z = Ya@Yb + Ya + Yb (deviations in, deviation out).
// ---------------------------------------------------------------------------
__device__ __forceinline__ void compose_to_tile(
    const unsigned* tabAa, const unsigned* tabAb, const unsigned* tabBb,
    float* zs, int lane) {
    const int tig = lane & 3, g = lane >> 2;
    unsigned a[16], ybA[16];
    {
        const uint4* pa = reinterpret_cast<const uint4*>(tabAa);
        const uint4* pb = reinterpret_cast<const uint4*>(tabAb);
        #pragma unroll
        for (int q = 0; q < 4; q++) {
            const uint4 va = pa[q * 32 + lane];
            a[4*q+0] = va.x; a[4*q+1] = va.y; a[4*q+2] = va.z; a[4*q+3] = va.w;
            const uint4 vb = pb[q * 32 + lane];
            ybA[4*q+0] = vb.x; ybA[4*q+1] = vb.y; ybA[4*q+2] = vb.z; ybA[4*q+3] = vb.w;
        }
    }
    const uint4* pbB = reinterpret_cast<const uint4*>(tabBb);
    const uint4 b0 = pbB[lane],      b1 = pbB[32 + lane];
    const uint4 b2 = pbB[64 + lane], b3 = pbB[96 + lane];

    float x[32];
    #pragma unroll
    for (int i = 0; i < 32; i++) x[i] = 0.f;
    mma_half(x, a, 0, b0, b1);
    mma_half(x, a, 4, b2, b3);

    #pragma unroll
    for (int ridx = 0; ridx < 16; ridx++) {
        const int mt = ridx >> 3, kc = (ridx >> 2) & 1, jj = ridx & 3;
        const int o = jj >> 1, ih = jj & 1;
        const int xi = mt * 16 + (2 * kc + o) * 4 + 2 * ih;
        const unsigned ua = a[ridx], ub = ybA[ridx];
        x[xi]     += __uint_as_float(ua << 16) + __uint_as_float(ub << 16);
        x[xi + 1] += __uint_as_float(ua & 0xFFFF0000u)
                   + __uint_as_float(ub & 0xFFFF0000u);
    }

    #pragma unroll
    for (int mt = 0; mt < 2; mt++)
        #pragma unroll
        for (int nt = 0; nt < 4; nt++)
            #pragma unroll
            for (int ih = 0; ih < 2; ih++) {
                const int row = g + 8 * ih + 16 * mt;
                const int col = 8 * nt + 2 * tig;
                *reinterpret_cast<float2*>(zs + row * 34 + col) =
                    make_float2(x[mt*16 + nt*4 + 2*ih], x[mt*16 + nt*4 + 2*ih + 1]);
            }
    __syncwarp();
}

template <bool WITH_A>
__device__ __forceinline__ void emit_entry(const float* zs, unsigned* outB,
                                           unsigned* outA, int lane) {
    const int tig = lane & 3, g = lane >> 2;
    #pragma unroll
    for (int q = 0; q < 4; q++) {
        unsigned v[4];
        #pragma unroll
        for (int j = 0; j < 4; j++) {
            const int ridx = 4 * q + j;
            const int kc = ridx >> 3, nt = (ridx >> 1) & 3, h = ridx & 1;
            const int row = 16 * kc + 2 * tig + 8 * h;
            const int col = 8 * nt + g;
            asm("cvt.rn.bf16x2.f32 %0, %1, %2;"
                : "=r"(v[j]) : "f"(zs[(row + 1) * 34 + col]), "f"(zs[row * 34 + col]));
        }
        *reinterpret_cast<uint4*>(outB + q * 128 + lane * 4) =
            make_uint4(v[0], v[1], v[2], v[3]);
        if (WITH_A) {
            unsigned w[4];
            #pragma unroll
            for (int j = 0; j < 4; j++) {
                const int ridx = 4 * q + j;
                const int mt = ridx >> 3, kc = (ridx >> 2) & 1, jj = ridx & 3;
                const int o = jj >> 1, ih = jj & 1;
                const int row = g + 8 * ih + 16 * mt;
                const int col = 8 * (2 * kc + o) + 2 * tig;
                asm("cvt.rn.bf16x2.f32 %0, %1, %2;"
                    : "=r"(w[j]) : "f"(zs[row * 34 + col + 1]), "f"(zs[row * 34 + col]));
            }
            *reinterpret_cast<uint4*>(outA + q * 128 + lane * 4) =
                make_uint4(w[0], w[1], w[2], w[3]);
        }
    }
}

// compose7: 7 = 4(low bits) o 3(high bits); 128 warps, emits B + A layouts
#define C7_WARPS 8
__global__ void __launch_bounds__(C7_WARPS * 32) compose7_kernel() {
    __shared__ float Zs[C7_WARPS][32 * 34];
    const int lane = threadIdx.x & 31;
    const int warp = threadIdx.x >> 5;
    const int code = blockIdx.x * C7_WARPS + warp;
    const int ca = code & 15;             // first 4 sites
    const int cb = code >> 4;             // next 3 sites
    compose_to_tile(g4A + ca * 512, g3A + cb * 512, g3B + cb * 512,
                    Zs[warp], lane);
    emit_entry<true>(Zs[warp], g7B + code * 512, g7A + code * 512, lane);
}

// build14: 14 = 7(low) o 7(high); 16384 warps, emits B layout only
#define B14_WARPS 8
__global__ void __launch_bounds__(B14_WARPS * 32) build14_kernel() {
    __shared__ float Zs[B14_WARPS][32 * 34];
    const int lane = threadIdx.x & 31;
    const int warp = threadIdx.x >> 5;
    const int code = blockIdx.x * B14_WARPS + warp;
    const int ca = code & 127;            // first 7 sites
    const int cb = code >> 7;             // next 7 sites
    compose_to_tile(g7A + ca * 512, g7A + cb * 512, g7B + cb * 512,
                    Zs[warp], lane);
    emit_entry<false>(Zs[warp], g14_table + code * 512, nullptr, lane);
}

// ---------------------------------------------------------------------------
// Main kernel: ONE sample per warp, 28 warps/CTA.
// 64 x 14-site (L2 stream, 3-stage cp.async ring, lookahead 2); first 32
// iterations also do a 4-site step from the 32KB smem table. 896+128 = 1024.
// ---------------------------------------------------------------------------
__device__ __forceinline__ void step_from(const uint4* p, float x[32],
                                          unsigned a[16], int lane) {
    const uint4 t0 = p[lane],      t1 = p[32 + lane];
    const uint4 t2 = p[64 + lane], t3 = p[96 + lane];
    mma_half(x, a, 0, t0, t1);
    mma_half(x, a, 4, t2, t3);
    cvt_a(a, x);
}

__device__ __forceinline__ void prefetch_entry(unsigned dst,
                                               const unsigned* entry, int lane) {
    const unsigned* sp = entry + lane * 4;
    const unsigned dp = dst + lane * 16;
    asm volatile(
        "cp.async.cg.shared.global [%0], [%1], 16;\n\t"
        "cp.async.cg.shared.global [%2], [%3], 16;\n\t"
        "cp.async.cg.shared.global [%4], [%5], 16;\n\t"
        "cp.async.cg.shared.global [%6], [%7], 16;\n\t"
        :: "r"(dp),        "l"(sp),
           "r"(dp + 512),  "l"(sp + 128),
           "r"(dp + 1024), "l"(sp + 256),
           "r"(dp + 1536), "l"(sp + 384)
        : "memory");
}
#define CP_COMMIT()  asm volatile("cp.async.commit_group;" ::: "memory")
#define CP_WAIT2()   asm volatile("cp.async.wait_group 2;" ::: "memory")

#define NWARPS 28
#define G4_BYTES (NB4 * 512 * 4)              // 32 KB
#define RING_OFF G4_BYTES
#define RING_BYTES (NWARPS * 3 * 2048)        // 168 KB, 3 stages / warp
#define MSK_OFF (RING_OFF + RING_BYTES)
#define MSK_BYTES (NWARPS * 32 * 4)           // 3.5 KB
#define CW14_OFF (MSK_OFF + MSK_BYTES)
#define CW14_BYTES (NWARPS * 64 * 2)          // 64 entries
#define CW4_OFF (CW14_OFF + CW14_BYTES)
#define CW4_BYTES (NWARPS * 32)               // 32 entries
#define SMEM_BYTES (CW4_OFF + CW4_BYTES)      // ~208 KB
#define GRID 148
#define NTHREADS (NWARPS * 32)                // 896

__global__ void __launch_bounds__(NTHREADS, 1)
mps_kernel(const float* __restrict__ s, float* __restrict__ out) {
    extern __shared__ unsigned char smem_raw[];
    uint4* g4tab = reinterpret_cast<uint4*>(smem_raw);
    const int lane = threadIdx.x & 31;
    const int warp = threadIdx.x >> 5;
    const int b = warp * GRID + blockIdx.x;   // one sample per warp
    const int g = lane >> 2, tig = lane & 3;

    {   // cooperative copy of the 4-site table
        const uint4* gt = reinterpret_cast<const uint4*>(g4B);
        for (int i = threadIdx.x; i < NB4 * 128; i += NTHREADS)
            g4tab[i] = gt[i];
    }

    unsigned* mw = reinterpret_cast<unsigned*>(smem_raw + MSK_OFF) + warp * 32;
    unsigned short* cw14 =
        reinterpret_cast<unsigned short*>(smem_raw + CW14_OFF) + warp * 64;
    unsigned char* cw4 = smem_raw + CW4_OFF + warp * 32;

    // Prologue (warp-private): masks -> code sequences
    // pair i<32: 14-bit code @ bit 18i, 4-bit code @ 18i+14
    // pair i>=32: 14-bit code @ bit 576 + 14(i-32);  576 + 448 = 1024
    if (b < 4096) {
        const float* srow = s + (size_t)b * NSITES;
        #pragma unroll 8
        for (int j = 0; j < 32; j++)
            mw[j] = __ballot_sync(0xffffffffu, srow[j * 32 + lane] > 0.f);
        __syncwarp();
        for (int t = lane; t < N14STEPS; t += 32) {
            int bit = (t < 32) ? 18 * t : 576 + 14 * (t - 32);
            int w = bit >> 5, sh = bit & 31;
            unsigned hi = (w < 31) ? mw[w + 1] : 0u;
            cw14[t] = (unsigned short)(__funnelshift_r(mw[w], hi, sh) & 0x3FFFu);
            if (t < 32) {
                bit += 14; w = bit >> 5; sh = bit & 31;
                hi = (w < 31) ? mw[w + 1] : 0u;
                cw4[t] = (unsigned char)(__funnelshift_r(mw[w], hi, sh) & 15u);
            }
        }
    }
    __syncthreads();            // g4 table ready
    if (b >= 4096) return;

    uint4* rp = reinterpret_cast<uint4*>(smem_raw + RING_OFF + warp * 6144);
    const unsigned ring_s = (unsigned)__cvta_generic_to_shared(rp);

    // Init M = I in C-fragment layout
    float x[32];
    #pragma unroll
    for (int mt = 0; mt < 2; mt++)
        #pragma unroll
        for (int nt = 0; nt < 4; nt++)
            #pragma unroll
            for (int i = 0; i < 4; i++) {
                const int row = g + 8 * (i >> 1) + 16 * mt;
                const int col = 8 * nt + 2 * tig + (i & 1);
                x[mt*16 + nt*4 + i] = (row == col) ? 1.f : 0.f;
            }

    // Ring prologue: stages 0,1,2 for steps 0,1,2
    prefetch_entry(ring_s,        g14_table + (int)cw14[0] * 512, lane);
    CP_COMMIT();
    prefetch_entry(ring_s + 2048, g14_table + (int)cw14[1] * 512, lane);
    CP_COMMIT();
    prefetch_entry(ring_s + 4096, g14_table + (int)cw14[2] * 512, lane);
    CP_COMMIT();
    unsigned a[16];
    cvt_a(a, x);

    int st = 0;
    for (int i = 0; i < N14STEPS; i++) {
        CP_WAIT2();                            // step i's stage is ready
        const uint4* p = rp + st * 128;
        const uint4 t0 = p[lane],      t1 = p[32 + lane];
        const uint4 t2 = p[64 + lane], t3 = p[96 + lane];
        if (i + 3 < N14STEPS)                  // refill the stage just read
            prefetch_entry(ring_s + st * 2048,
                           g14_table + (int)cw14[i + 3] * 512, lane);
        CP_COMMIT();                           // uniform group accounting
        mma_half(x, a, 0, t0, t1);             // 14-site step
        mma_half(x, a, 4, t2, t3);
        cvt_a(a, x);
        if (i < N4STEPS)
            step_from(g4tab + (int)cw4[i] * 128, x, a, lane);   // 4-site step
        st++; if (st == 3) st = 0;
    }

    // trace(M)
    float tr = 0.f;
    #pragma unroll
    for (int mt = 0; mt < 2; mt++)
        #pragma unroll
        for (int nt = 0; nt < 4; nt++)
            #pragma unroll
            for (int i = 0; i < 4; i++) {
                const int row = g + 8 * (i >> 1) + 16 * mt;
                const int col = 8 * nt + 2 * tig + (i & 1);
                if (row == col) tr += x[mt*16 + nt*4 + i];
            }
    #pragma unroll
    for (int off = 16; off; off >>= 1)
        tr += __shfl_xor_sync(0xffffffffu, tr, off);

    if (lane == 0) out[b] = logf(tr);
}

// ---------------------------------------------------------------------------
extern "C" void kernel_launch(void* const* d_in, const int* in_sizes, int n_in,
                              void* d_out, int out_size) {
    const float* s = (const float*)d_in[0];   // [4096, 1024] fp32
    const float* A = (const float*)d_in[1];   // [2, 32, 32] fp32
    float* out = (float*)d_out;               // [4096] fp32

    static bool attr_set = false;
    if (!attr_set) {
        cudaFuncSetAttribute(mps_kernel,
                             cudaFuncAttributeMaxDynamicSharedMemorySize,
                             SMEM_BYTES);
        attr_set = true;
    }

    build_base_kernel<<<NB3 + NB4, 1024>>>(A);
    compose7_kernel<<<NC7 / C7_WARPS, C7_WARPS * 32>>>();
    build14_kernel<<<N14 / B14_WARPS, B14_WARPS * 32>>>();
    mps_kernel<<<GRID, NTHREADS, SMEM_BYTES>>>(s, out);
}